// round 14
// baseline (speedup 1.0000x reference)
#include <cuda_runtime.h>
#include <cuda_bf16.h>

#define S_LEN 2048
#define B_SZ  16
#define H_DIM 1024
#define VPS   8                        // s-rows per score block
#define BLKS_PER_COL (S_LEN / VPS)     // 256

// 8 chunk-partial slabs (race-free -> no init kernel)
__device__ float g_part[8][B_SZ * H_DIM];
__device__ float g_scoresT[B_SZ * S_LEN];   // transposed scores [b][s]
__device__ int   g_cnt[B_SZ];               // per-column completion counters
                                            // (zero-init, self-resetting)

// ---------------------------------------------------------------------------
// Kernel 1 (R8-proven): energy partials. j in 8 chunks of 128 floats.
// Block = 128 thr (4 warps) covers (8 h-rows) x (one chunk); warp owns
// 2 rows x 16 b = 32 accumulators, each LDS.128 feeds 8 FFMAs. grid=1024.
// ---------------------------------------------------------------------------
__global__ void __launch_bounds__(128)
energy_kernel(const float* __restrict__ lds,
              const float* __restrict__ W)
{
    __shared__ float4 s_st[16 * 32];     // [b][32 float4] (8KB)

    const int t    = threadIdx.x;
    const int warp = t >> 5;
    const int lane = t & 31;
    const int rg   = blockIdx.x >> 3;
    const int ch   = blockIdx.x & 7;
    const int row0 = rg * 8 + warp * 2;

    const float4* st4 = reinterpret_cast<const float4*>(lds);  // [B][256]
    const float4* W4  = reinterpret_cast<const float4*>(W);    // [H][256]

    const float4 w0 = W4[(size_t)row0 * 256 + ch * 32 + lane];
    const float4 w1 = W4[(size_t)(row0 + 1) * 256 + ch * 32 + lane];

    #pragma unroll
    for (int i = 0; i < 4; ++i) {
        const int v = t + i * 128;
        const int b = v >> 5;
        const int k = v & 31;
        s_st[v] = st4[b * 256 + ch * 32 + k];
    }
    __syncthreads();

    float a[32];                          // a[r*16+b]
    #pragma unroll
    for (int b = 0; b < 16; ++b) {
        const float4 s = s_st[b * 32 + lane];
        a[b]      = w0.x * s.x + w0.y * s.y + w0.z * s.z + w0.w * s.w;
        a[16 + b] = w1.x * s.x + w1.y * s.y + w1.z * s.z + w1.w * s.w;
    }

    // Value-halving butterfly: lane l ends holding warp-total of a[l].
    int n = 32;
    #pragma unroll
    for (int s = 16; s >= 1; s >>= 1) {
        const int  half = n >> 1;
        const bool up   = (lane & s) != 0;
        #pragma unroll
        for (int i = 0; i < half; ++i) {
            const float send = up ? a[i] : a[i + half];
            const float keep = up ? a[i + half] : a[i];
            a[i] = keep + __shfl_xor_sync(0xFFFFFFFF, send, s);
        }
        n = half;
    }

    const int r = lane >> 4;
    const int b = lane & 15;
    g_part[ch][(size_t)b * H_DIM + row0 + r] = a[0];
}

// ---------------------------------------------------------------------------
// Kernel 2: score + tail-fused softmax.
// Each block: scores for (b, 8-row s-chunk) -> g_scoresT, then per-column
// completion count. The LAST block of a column runs that column's softmax:
// 3 L2-hot passes (max, exp-sum, scale+store to out). No softmax launch.
// ---------------------------------------------------------------------------
__global__ void __launch_bounds__(128)
score_kernel(const float* __restrict__ enc,
             const float* __restrict__ bias,
             float* __restrict__ out)
{
    const int b  = blockIdx.x & (B_SZ - 1);
    const int s0 = (blockIdx.x >> 4) * VPS;
    const int t  = threadIdx.x;
    const int warp = t >> 5;
    const int lane = t & 31;

    const float4* e4 = reinterpret_cast<const float4*>(enc);
    const float4* b4 = reinterpret_cast<const float4*>(bias);

    float4 g0 = b4[t];
    float4 g1 = b4[128 + t];
    #pragma unroll
    for (int c = 0; c < 8; ++c) {
        const float4* p4 = reinterpret_cast<const float4*>(g_part[c]);
        const float4 p0 = p4[b * (H_DIM / 4) + t];
        const float4 p1 = p4[b * (H_DIM / 4) + 128 + t];
        g0.x += p0.x; g0.y += p0.y; g0.z += p0.z; g0.w += p0.w;
        g1.x += p1.x; g1.y += p1.y; g1.z += p1.z; g1.w += p1.w;
    }

    float acc[VPS];
    #pragma unroll
    for (int i = 0; i < VPS; ++i) {
        const size_t row = ((size_t)(s0 + i) * B_SZ + b) * (H_DIM / 4);
        const float4 a0 = e4[row + t];
        const float4 a1 = e4[row + 128 + t];
        acc[i] = a0.x * g0.x + a0.y * g0.y + a0.z * g0.z + a0.w * g0.w
               + a1.x * g1.x + a1.y * g1.y + a1.z * g1.z + a1.w * g1.w;
    }

    #pragma unroll
    for (int i = 0; i < VPS; ++i)
        #pragma unroll
        for (int off = 16; off > 0; off >>= 1)
            acc[i] += __shfl_xor_sync(0xFFFFFFFF, acc[i], off);

    __shared__ float red[4][VPS];
    __shared__ int   s_last;
    if (lane == 0) {
        #pragma unroll
        for (int i = 0; i < VPS; ++i)
            red[warp][i] = acc[i];
    }
    __syncthreads();
    if (t < VPS)
        g_scoresT[(size_t)b * S_LEN + s0 + t] =
            red[0][t] + red[1][t] + red[2][t] + red[3][t];

    // Publish this block's stores, then count completion for column b.
    __threadfence();
    __syncthreads();
    if (t == 0) {
        const int old = atomicAdd(&g_cnt[b], 1);
        s_last = (old == BLKS_PER_COL - 1);
    }
    __syncthreads();
    if (!s_last) return;

    // ====== This is the last block for column b: run its softmax. ======
    __threadfence();   // acquire: make all columns' score stores visible
    const float4* c4 = reinterpret_cast<const float4*>(g_scoresT + (size_t)b * S_LEN);
    __shared__ float sm[4];

    // Pass 1: max
    float mx = -3.402823466e38f;
    #pragma unroll
    for (int i = 0; i < 4; ++i) {
        const float4 v = c4[t + i * 128];
        mx = fmaxf(mx, fmaxf(fmaxf(v.x, v.y), fmaxf(v.z, v.w)));
    }
    #pragma unroll
    for (int off = 16; off > 0; off >>= 1)
        mx = fmaxf(mx, __shfl_xor_sync(0xFFFFFFFF, mx, off));
    if (lane == 0) sm[warp] = mx;
    __syncthreads();
    mx = fmaxf(fmaxf(sm[0], sm[1]), fmaxf(sm[2], sm[3]));

    // Pass 2: exp-sum
    float sum = 0.f;
    #pragma unroll
    for (int i = 0; i < 4; ++i) {
        const float4 v = c4[t + i * 128];
        sum += __expf(v.x - mx) + __expf(v.y - mx)
             + __expf(v.z - mx) + __expf(v.w - mx);
    }
    #pragma unroll
    for (int off = 16; off > 0; off >>= 1)
        sum += __shfl_xor_sync(0xFFFFFFFF, sum, off);
    __syncthreads();
    if (lane == 0) sm[warp] = sum;
    __syncthreads();
    const float inv = 1.0f / (sm[0] + sm[1] + sm[2] + sm[3]);

    // Pass 3: scale + store to out[s][b]
    #pragma unroll
    for (int i = 0; i < 4; ++i) {
        const int   idx = t + i * 128;        // float4 index -> s = 4*idx..
        const float4 v  = c4[idx];
        const int   s   = idx * 4;
        out[(size_t)(s + 0) * B_SZ + b] = __expf(v.x - mx) * inv;
        out[(size_t)(s + 1) * B_SZ + b] = __expf(v.y - mx) * inv;
        out[(size_t)(s + 2) * B_SZ + b] = __expf(v.z - mx) * inv;
        out[(size_t)(s + 3) * B_SZ + b] = __expf(v.w - mx) * inv;
    }

    // Re-arm counter for the next graph replay.
    if (t == 0) g_cnt[b] = 0;
}

// ---------------------------------------------------------------------------
extern "C" void kernel_launch(void* const* d_in, const int* in_sizes, int n_in,
                              void* d_out, int out_size)
{
    const float* enc  = (const float*)d_in[0];  // [S,B,H]
    const float* lds  = (const float*)d_in[1];  // [2,1,B,H]
    const float* W    = (const float*)d_in[2];  // [H,H]
    const float* bias = (const float*)d_in[3];  // [H]
    float* out = (float*)d_out;                 // [1,1,S,B] == [S,B]

    energy_kernel<<<1024, 128>>>(lds, W);
    score_kernel<<<(S_LEN / VPS) * B_SZ, 128>>>(enc, bias, out);
}

// round 15
// speedup vs baseline: 1.0576x; 1.0576x over previous
#include <cuda_runtime.h>
#include <cuda_bf16.h>

#define S_LEN 2048
#define B_SZ  16
#define H_DIM 1024
#define VPS   8                        // s-rows per score block
#define BLKS_PER_COL (S_LEN / VPS)     // 256

// 8 chunk-partial slabs (race-free -> no init kernel)
__device__ float g_part[8][B_SZ * H_DIM];
__device__ float g_scoresT[B_SZ * S_LEN];   // transposed scores [b][s]
__device__ int   g_cnt[B_SZ * 64];          // per-column counters, 256B apart
                                            // (zero-init, self-resetting)

// ---------------------------------------------------------------------------
// Kernel 1 (R8-proven): energy partials. j in 8 chunks of 128 floats.
// Block = 128 thr (4 warps) covers (8 h-rows) x (one chunk); warp owns
// 2 rows x 16 b = 32 accumulators, each LDS.128 feeds 8 FFMAs. grid=1024.
// ---------------------------------------------------------------------------
__global__ void __launch_bounds__(128)
energy_kernel(const float* __restrict__ lds,
              const float* __restrict__ W)
{
    __shared__ float4 s_st[16 * 32];     // [b][32 float4] (8KB)

    const int t    = threadIdx.x;
    const int warp = t >> 5;
    const int lane = t & 31;
    const int rg   = blockIdx.x >> 3;
    const int ch   = blockIdx.x & 7;
    const int row0 = rg * 8 + warp * 2;

    const float4* st4 = reinterpret_cast<const float4*>(lds);  // [B][256]
    const float4* W4  = reinterpret_cast<const float4*>(W);    // [H][256]

    const float4 w0 = W4[(size_t)row0 * 256 + ch * 32 + lane];
    const float4 w1 = W4[(size_t)(row0 + 1) * 256 + ch * 32 + lane];

    #pragma unroll
    for (int i = 0; i < 4; ++i) {
        const int v = t + i * 128;
        const int b = v >> 5;
        const int k = v & 31;
        s_st[v] = st4[b * 256 + ch * 32 + k];
    }
    __syncthreads();

    float a[32];                          // a[r*16+b]
    #pragma unroll
    for (int b = 0; b < 16; ++b) {
        const float4 s = s_st[b * 32 + lane];
        a[b]      = w0.x * s.x + w0.y * s.y + w0.z * s.z + w0.w * s.w;
        a[16 + b] = w1.x * s.x + w1.y * s.y + w1.z * s.z + w1.w * s.w;
    }

    // Value-halving butterfly: lane l ends holding warp-total of a[l].
    int n = 32;
    #pragma unroll
    for (int s = 16; s >= 1; s >>= 1) {
        const int  half = n >> 1;
        const bool up   = (lane & s) != 0;
        #pragma unroll
        for (int i = 0; i < half; ++i) {
            const float send = up ? a[i] : a[i + half];
            const float keep = up ? a[i + half] : a[i];
            a[i] = keep + __shfl_xor_sync(0xFFFFFFFF, send, s);
        }
        n = half;
    }

    const int r = lane >> 4;
    const int b = lane & 15;
    g_part[ch][(size_t)b * H_DIM + row0 + r] = a[0];
}

// ---------------------------------------------------------------------------
// Kernel 2: score + tail-fused softmax (fixed sync cost).
// Each block: scores for (b, 8-row s-chunk) -> g_scoresT; ONLY the 8 storing
// threads fence; single t0 atomic on a 256B-strided counter. The LAST block
// of a column runs that column's softmax (3 L2-hot passes). No 3rd kernel.
// ---------------------------------------------------------------------------
__global__ void __launch_bounds__(128)
score_kernel(const float* __restrict__ enc,
             const float* __restrict__ bias,
             float* __restrict__ out)
{
    const int b  = blockIdx.x & (B_SZ - 1);
    const int s0 = (blockIdx.x >> 4) * VPS;
    const int t  = threadIdx.x;
    const int warp = t >> 5;
    const int lane = t & 31;

    const float4* e4 = reinterpret_cast<const float4*>(enc);
    const float4* b4 = reinterpret_cast<const float4*>(bias);

    float4 g0 = b4[t];
    float4 g1 = b4[128 + t];
    #pragma unroll
    for (int c = 0; c < 8; ++c) {
        const float4* p4 = reinterpret_cast<const float4*>(g_part[c]);
        const float4 p0 = p4[b * (H_DIM / 4) + t];
        const float4 p1 = p4[b * (H_DIM / 4) + 128 + t];
        g0.x += p0.x; g0.y += p0.y; g0.z += p0.z; g0.w += p0.w;
        g1.x += p1.x; g1.y += p1.y; g1.z += p1.z; g1.w += p1.w;
    }

    float acc[VPS];
    #pragma unroll
    for (int i = 0; i < VPS; ++i) {
        const size_t row = ((size_t)(s0 + i) * B_SZ + b) * (H_DIM / 4);
        const float4 a0 = e4[row + t];
        const float4 a1 = e4[row + 128 + t];
        acc[i] = a0.x * g0.x + a0.y * g0.y + a0.z * g0.z + a0.w * g0.w
               + a1.x * g1.x + a1.y * g1.y + a1.z * g1.z + a1.w * g1.w;
    }

    #pragma unroll
    for (int i = 0; i < VPS; ++i)
        #pragma unroll
        for (int off = 16; off > 0; off >>= 1)
            acc[i] += __shfl_xor_sync(0xFFFFFFFF, acc[i], off);

    __shared__ float red[4][VPS];
    __shared__ int   s_last;
    if (lane == 0) {
        #pragma unroll
        for (int i = 0; i < VPS; ++i)
            red[warp][i] = acc[i];
    }
    __syncthreads();
    if (t < VPS) {
        g_scoresT[(size_t)b * S_LEN + s0 + t] =
            red[0][t] + red[1][t] + red[2][t] + red[3][t];
        __threadfence();                 // release: only the 8 storing threads
    }
    __syncthreads();
    if (t == 0) {
        const int old = atomicAdd(&g_cnt[b * 64], 1);
        s_last = (old == BLKS_PER_COL - 1);
    }
    __syncthreads();
    if (!s_last) return;

    // ====== Last block for column b: run its softmax (L2-hot). ======
    __threadfence();                     // acquire all columns' score stores
    const float4* c4 = reinterpret_cast<const float4*>(g_scoresT + (size_t)b * S_LEN);
    __shared__ float sm[4];

    // Pass 1: max
    float mx = -3.402823466e38f;
    #pragma unroll
    for (int i = 0; i < 4; ++i) {
        const float4 v = c4[t + i * 128];
        mx = fmaxf(mx, fmaxf(fmaxf(v.x, v.y), fmaxf(v.z, v.w)));
    }
    #pragma unroll
    for (int off = 16; off > 0; off >>= 1)
        mx = fmaxf(mx, __shfl_xor_sync(0xFFFFFFFF, mx, off));
    if (lane == 0) sm[warp] = mx;
    __syncthreads();
    mx = fmaxf(fmaxf(sm[0], sm[1]), fmaxf(sm[2], sm[3]));

    // Pass 2: exp-sum
    float sum = 0.f;
    #pragma unroll
    for (int i = 0; i < 4; ++i) {
        const float4 v = c4[t + i * 128];
        sum += __expf(v.x - mx) + __expf(v.y - mx)
             + __expf(v.z - mx) + __expf(v.w - mx);
    }
    #pragma unroll
    for (int off = 16; off > 0; off >>= 1)
        sum += __shfl_xor_sync(0xFFFFFFFF, sum, off);
    __syncthreads();
    if (lane == 0) sm[warp] = sum;
    __syncthreads();
    const float inv = 1.0f / (sm[0] + sm[1] + sm[2] + sm[3]);

    // Pass 3: scale + store to out[s][b]
    #pragma unroll
    for (int i = 0; i < 4; ++i) {
        const int    idx = t + i * 128;       // float4 index -> s = 4*idx..
        const float4 v   = c4[idx];
        const int    s   = idx * 4;
        out[(size_t)(s + 0) * B_SZ + b] = __expf(v.x - mx) * inv;
        out[(size_t)(s + 1) * B_SZ + b] = __expf(v.y - mx) * inv;
        out[(size_t)(s + 2) * B_SZ + b] = __expf(v.z - mx) * inv;
        out[(size_t)(s + 3) * B_SZ + b] = __expf(v.w - mx) * inv;
    }

    // Re-arm counter for the next graph replay.
    if (t == 0) g_cnt[b * 64] = 0;
}

// ---------------------------------------------------------------------------
extern "C" void kernel_launch(void* const* d_in, const int* in_sizes, int n_in,
                              void* d_out, int out_size)
{
    const float* enc  = (const float*)d_in[0];  // [S,B,H]
    const float* lds  = (const float*)d_in[1];  // [2,1,B,H]
    const float* W    = (const float*)d_in[2];  // [H,H]
    const float* bias = (const float*)d_in[3];  // [H]
    float* out = (float*)d_out;                 // [1,1,S,B] == [S,B]

    energy_kernel<<<1024, 128>>>(lds, W);
    score_kernel<<<(S_LEN / VPS) * B_SZ, 128>>>(enc, bias, out);
}

// round 16
// speedup vs baseline: 1.1291x; 1.0676x over previous
#include <cuda_runtime.h>
#include <cuda_bf16.h>
#include <cstdint>

#define S_LEN 2048
#define B_SZ  16
#define H_DIM 1024
#define VPS   8                        // s-rows per score block

// 4 chunk-partial slabs (race-free -> no init kernel)  [R7 layout]
__device__ float g_part[4][B_SZ * H_DIM];
__device__ float g_scoresT[B_SZ * S_LEN];   // transposed scores [b][s]

// ---------------- cp.async helpers ----------------
__device__ __forceinline__ void cp_async16(uint32_t saddr, const void* gptr) {
    asm volatile("cp.async.cg.shared.global [%0], [%1], 16;"
                 :: "r"(saddr), "l"(gptr));
}
__device__ __forceinline__ void cp_async_commit() {
    asm volatile("cp.async.commit_group;");
}
__device__ __forceinline__ void cp_async_wait_all() {
    asm volatile("cp.async.wait_group 0;" ::: "memory");
}

// ---------------------------------------------------------------------------
// Kernel 1 (R7-proven, 6.46us): energy partials. j in 4 chunks of 256 floats.
// Block = 128 thr (4 warps) covers (8 h-rows) x (one chunk); warp owns
// 2 rows x 16 b = 32 accumulators. grid = 512. Triggers PDL at entry.
// ---------------------------------------------------------------------------
__global__ void __launch_bounds__(128)
energy_kernel(const float* __restrict__ lds,
              const float* __restrict__ W)
{
#if __CUDA_ARCH__ >= 900
    cudaTriggerProgrammaticLaunchCompletion();
#endif
    __shared__ float4 s_st[16 * 64];     // [b][64 float4] (16KB)

    const int t    = threadIdx.x;
    const int warp = t >> 5;
    const int lane = t & 31;
    const int rg   = blockIdx.x >> 2;    // 8-row group
    const int ch   = blockIdx.x & 3;     // j-chunk (256 floats = 64 float4)
    const int row0 = rg * 8 + warp * 2;

    const float4* st4 = reinterpret_cast<const float4*>(lds);  // [B][256]
    const float4* W4  = reinterpret_cast<const float4*>(W);    // [H][256]

    #pragma unroll
    for (int i = 0; i < 8; ++i) {
        const int v = t + i * 128;       // 0..1023
        const int b = v >> 6;
        const int k = v & 63;
        s_st[v] = st4[b * 256 + ch * 64 + k];
    }
    __syncthreads();

    float a[32];                          // a[r*16+b]
    #pragma unroll
    for (int v = 0; v < 32; ++v) a[v] = 0.f;

    #pragma unroll
    for (int u = 0; u < 2; ++u) {
        const int idx = u * 32 + lane;
        const float4 w0 = W4[(size_t)row0 * 256 + ch * 64 + idx];
        const float4 w1 = W4[(size_t)(row0 + 1) * 256 + ch * 64 + idx];
        #pragma unroll
        for (int b = 0; b < 16; ++b) {
            const float4 s = s_st[b * 64 + idx];
            a[b]      += w0.x * s.x + w0.y * s.y + w0.z * s.z + w0.w * s.w;
            a[16 + b] += w1.x * s.x + w1.y * s.y + w1.z * s.z + w1.w * s.w;
        }
    }

    // Value-halving butterfly: lane l ends holding warp-total of a[l].
    int n = 32;
    #pragma unroll
    for (int s = 16; s >= 1; s >>= 1) {
        const int  half = n >> 1;
        const bool up   = (lane & s) != 0;
        #pragma unroll
        for (int i = 0; i < half; ++i) {
            const float send = up ? a[i] : a[i + half];
            const float keep = up ? a[i + half] : a[i];
            a[i] = keep + __shfl_xor_sync(0xFFFFFFFF, send, s);
        }
        n = half;
    }

    const int r = lane >> 4;
    const int b = lane & 15;
    g_part[ch][(size_t)b * H_DIM + row0 + r] = a[0];
}

// ---------------------------------------------------------------------------
// Kernel 2: scores. Launched with PDL: blocks start DURING energy, prefetch
// their 32KB enc tile via cp.async.cg into smem (overlaps energy), then
// cudaGridDependencySynchronize() before folding bias+partials.
// Each thread consumes only the smem it fetched -> no extra block sync.
// ---------------------------------------------------------------------------
__global__ void __launch_bounds__(128)
score_kernel(const float* __restrict__ enc,
             const float* __restrict__ bias)
{
#if __CUDA_ARCH__ >= 900
    cudaTriggerProgrammaticLaunchCompletion();
#endif
    __shared__ float4 s_enc[16 * 128];   // 32KB: [k][t]

    const int b  = blockIdx.x & (B_SZ - 1);
    const int s0 = (blockIdx.x >> 4) * VPS;
    const int t  = threadIdx.x;
    const int warp = t >> 5;
    const int lane = t & 31;

    const float4* e4 = reinterpret_cast<const float4*>(enc);
    const float4* b4 = reinterpret_cast<const float4*>(bias);

    // Prefetch: k = 2*i + half; global row = ((s0+i)*B + b) * 256
    const uint32_t sbase = (uint32_t)__cvta_generic_to_shared(s_enc);
    #pragma unroll
    for (int k = 0; k < 16; ++k) {
        const int    i   = k >> 1;
        const int    hl  = k & 1;
        const size_t row = ((size_t)(s0 + i) * B_SZ + b) * (H_DIM / 4);
        cp_async16(sbase + (uint32_t)(k * 128 + t) * 16,
                   (const void*)(e4 + row + hl * 128 + t));
    }
    cp_async_commit();

#if __CUDA_ARCH__ >= 900
    cudaGridDependencySynchronize();     // wait for energy (visibility incl.)
#endif

    // Fold energy row: bias + 4 partial slabs (L2-hot).
    float4 g0 = b4[t];
    float4 g1 = b4[128 + t];
    #pragma unroll
    for (int c = 0; c < 4; ++c) {
        const float4* p4 = reinterpret_cast<const float4*>(g_part[c]);
        const float4 p0 = p4[b * (H_DIM / 4) + t];
        const float4 p1 = p4[b * (H_DIM / 4) + 128 + t];
        g0.x += p0.x; g0.y += p0.y; g0.z += p0.z; g0.w += p0.w;
        g1.x += p1.x; g1.y += p1.y; g1.z += p1.z; g1.w += p1.w;
    }

    cp_async_wait_all();                 // enc tile resident in smem

    float acc[VPS];
    #pragma unroll
    for (int i = 0; i < VPS; ++i) {
        const float4 a0 = s_enc[(2 * i)     * 128 + t];
        const float4 a1 = s_enc[(2 * i + 1) * 128 + t];
        acc[i] = a0.x * g0.x + a0.y * g0.y + a0.z * g0.z + a0.w * g0.w
               + a1.x * g1.x + a1.y * g1.y + a1.z * g1.z + a1.w * g1.w;
    }

    #pragma unroll
    for (int i = 0; i < VPS; ++i)
        #pragma unroll
        for (int off = 16; off > 0; off >>= 1)
            acc[i] += __shfl_xor_sync(0xFFFFFFFF, acc[i], off);

    __shared__ float red[4][VPS];
    if (lane == 0) {
        #pragma unroll
        for (int i = 0; i < VPS; ++i)
            red[warp][i] = acc[i];
    }
    __syncthreads();
    if (t < VPS)
        g_scoresT[(size_t)b * S_LEN + s0 + t] =
            red[0][t] + red[1][t] + red[2][t] + red[3][t];
}

// ---------------------------------------------------------------------------
// Kernel 3 (R12-proven body): softmax from g_scoresT, PDL-overlapped launch.
// ---------------------------------------------------------------------------
__global__ void __launch_bounds__(256)
softmax_kernel(float* __restrict__ out)
{
#if __CUDA_ARCH__ >= 900
    cudaGridDependencySynchronize();
#endif
    const int b = blockIdx.x;
    const int t = threadIdx.x;

    const float4* s4 = reinterpret_cast<const float4*>(g_scoresT + (size_t)b * S_LEN);
    float4 v0 = s4[t];
    float4 v1 = s4[t + 256];

    __shared__ float sm[8];
    const int warp = t >> 5, lane = t & 31;

    float mx = fmaxf(fmaxf(fmaxf(v0.x, v0.y), fmaxf(v0.z, v0.w)),
                     fmaxf(fmaxf(v1.x, v1.y), fmaxf(v1.z, v1.w)));
    #pragma unroll
    for (int off = 16; off > 0; off >>= 1)
        mx = fmaxf(mx, __shfl_xor_sync(0xFFFFFFFF, mx, off));
    if (lane == 0) sm[warp] = mx;
    __syncthreads();
    if (warp == 0) {
        float m = (lane < 8) ? sm[lane] : -3.402823466e38f;
        #pragma unroll
        for (int off = 4; off > 0; off >>= 1)
            m = fmaxf(m, __shfl_xor_sync(0xFFFFFFFF, m, off));
        if (lane == 0) sm[0] = m;
    }
    __syncthreads();
    mx = sm[0];
    __syncthreads();

    v0.x = __expf(v0.x - mx); v0.y = __expf(v0.y - mx);
    v0.z = __expf(v0.z - mx); v0.w = __expf(v0.w - mx);
    v1.x = __expf(v1.x - mx); v1.y = __expf(v1.y - mx);
    v1.z = __expf(v1.z - mx); v1.w = __expf(v1.w - mx);

    float sum = v0.x + v0.y + v0.z + v0.w + v1.x + v1.y + v1.z + v1.w;
    #pragma unroll
    for (int off = 16; off > 0; off >>= 1)
        sum += __shfl_xor_sync(0xFFFFFFFF, sum, off);
    if (lane == 0) sm[warp] = sum;
    __syncthreads();
    if (warp == 0) {
        float s = (lane < 8) ? sm[lane] : 0.f;
        #pragma unroll
        for (int off = 4; off > 0; off >>= 1)
            s += __shfl_xor_sync(0xFFFFFFFF, s, off);
        if (lane == 0) sm[0] = s;
    }
    __syncthreads();
    const float inv = 1.0f / sm[0];

    const int sA = t * 4;
    const int sB = 1024 + t * 4;
    out[(size_t)(sA + 0) * B_SZ + b] = v0.x * inv;
    out[(size_t)(sA + 1) * B_SZ + b] = v0.y * inv;
    out[(size_t)(sA + 2) * B_SZ + b] = v0.z * inv;
    out[(size_t)(sA + 3) * B_SZ + b] = v0.w * inv;
    out[(size_t)(sB + 0) * B_SZ + b] = v1.x * inv;
    out[(size_t)(sB + 1) * B_SZ + b] = v1.y * inv;
    out[(size_t)(sB + 2) * B_SZ + b] = v1.z * inv;
    out[(size_t)(sB + 3) * B_SZ + b] = v1.w * inv;
}

// ---------------------------------------------------------------------------
extern "C" void kernel_launch(void* const* d_in, const int* in_sizes, int n_in,
                              void* d_out, int out_size)
{
    const float* enc  = (const float*)d_in[0];  // [S,B,H]
    const float* lds  = (const float*)d_in[1];  // [2,1,B,H]
    const float* W    = (const float*)d_in[2];  // [H,H]
    const float* bias = (const float*)d_in[3];  // [H]
    float* out = (float*)d_out;                 // [1,1,S,B] == [S,B]

    // 1) energy: plain launch (triggers PDL completion at entry)
    energy_kernel<<<512, 128>>>(lds, W);

    // 2) score: PDL — may begin during energy; gridsyncs before using partials
    {
        cudaLaunchConfig_t cfg = {};
        cfg.gridDim  = dim3((S_LEN / VPS) * B_SZ, 1, 1);
        cfg.blockDim = dim3(128, 1, 1);
        cfg.stream   = 0;
        cudaLaunchAttribute attr[1];
        attr[0].id = cudaLaunchAttributeProgrammaticStreamSerialization;
        attr[0].val.programmaticStreamSerializationAllowed = 1;
        cfg.attrs = attr;
        cfg.numAttrs = 1;
        cudaLaunchKernelEx(&cfg, score_kernel, enc, bias);
    }

    // 3) softmax: PDL — launch overlaps score tail; gridsyncs before reading
    {
        cudaLaunchConfig_t cfg = {};
        cfg.gridDim  = dim3(B_SZ, 1, 1);
        cfg.blockDim = dim3(256, 1, 1);
        cfg.stream   = 0;
        cudaLaunchAttribute attr[1];
        attr[0].id = cudaLaunchAttributeProgrammaticStreamSerialization;
        attr[0].val.programmaticStreamSerializationAllowed = 1;
        cfg.attrs = attr;
        cfg.numAttrs = 1;
        cudaLaunchKernelEx(&cfg, softmax_kernel, out);
    }
}